// round 4
// baseline (speedup 1.0000x reference)
#include <cuda_runtime.h>
#include <math.h>

// Problem constants
#define L_   32
#define B_   4
#define N_   1000
#define D_   128
#define K_   8
#define H_   8
#define DH_  16
#define M_   (L_ * B_ * N_)   // 128000 tokens
#define PROJW 768             // q|k|v|sq|sk|sv concatenated per token

// Scratch (device globals: allocation-free, graph-capturable)
__device__ float g_proj[(size_t)M_ * PROJW];  // ~393 MB
__device__ float g_o  [(size_t)M_ * D_];      // temporal attn output
__device__ float g_so [(size_t)M_ * D_];      // spatial attn output
__device__ float g_w  [PROJW * D_];           // concat weights [768][128]
__device__ float g_b  [PROJW];                // concat in-biases
__device__ float g_ob [D_];                   // t_out_b + s_out_b

// ---------------------------------------------------------------------------
// Pack weights/biases into contiguous buffers
// ---------------------------------------------------------------------------
__global__ void prep_weights(const float* __restrict__ t_in_w,
                             const float* __restrict__ t_in_b,
                             const float* __restrict__ s_in_w,
                             const float* __restrict__ s_in_b,
                             const float* __restrict__ t_out_b,
                             const float* __restrict__ s_out_b)
{
    int i = blockIdx.x * 256 + threadIdx.x;
    const int NW = 384 * 128;
    if (i < NW) {
        g_w[i] = t_in_w[i];
    } else if (i < 2 * NW) {
        g_w[i] = s_in_w[i - NW];
    } else {
        int j = i - 2 * NW;
        if (j < 384)      g_b[j] = t_in_b[j];
        else if (j < 768) g_b[j] = s_in_b[j - 384];
        else if (j < 896) g_ob[j - 768] = t_out_b[j - 768] + s_out_b[j - 768];
    }
}

// ---------------------------------------------------------------------------
// SGEMM (NT): C[m][n] = sum_k A[m][k] * B[n][k] (+ bias[n]) (+= C if ACC)
// A: M x 128 row-major, Bw: Nn x 128 row-major. 128x128 tile, BK=8, 256 thr.
// M, Nn multiples of 128. K fixed at 128.
// ---------------------------------------------------------------------------
template<bool ACC, bool BIAS>
__global__ void __launch_bounds__(256) sgemm_nt(const float* __restrict__ A,
                                                const float* __restrict__ Bw,
                                                const float* __restrict__ bias,
                                                float* __restrict__ C,
                                                int Nn)
{
    const int Kd = 128;
    __shared__ float As[8][128];
    __shared__ float Bs[8][128];

    int tid = threadIdx.x;
    int tx = tid & 15;       // 0..15  -> N
    int ty = tid >> 4;       // 0..15  -> M

    int lrow = tid >> 1;         // 0..127 row within tile
    int lc   = (tid & 1) * 4;    // 0 or 4 (k offset)

    const float* Ap = A  + ((size_t)blockIdx.y * 128 + lrow) * Kd + lc;
    const float* Bp = Bw + ((size_t)blockIdx.x * 128 + lrow) * Kd + lc;

    float acc[8][8];
    #pragma unroll
    for (int i = 0; i < 8; i++)
        #pragma unroll
        for (int j = 0; j < 8; j++) acc[i][j] = 0.f;

    for (int k0 = 0; k0 < Kd; k0 += 8) {
        float4 av = *(const float4*)(Ap + k0);
        float4 bv = *(const float4*)(Bp + k0);
        As[lc + 0][lrow] = av.x; As[lc + 1][lrow] = av.y;
        As[lc + 2][lrow] = av.z; As[lc + 3][lrow] = av.w;
        Bs[lc + 0][lrow] = bv.x; Bs[lc + 1][lrow] = bv.y;
        Bs[lc + 2][lrow] = bv.z; Bs[lc + 3][lrow] = bv.w;
        __syncthreads();

        #pragma unroll
        for (int kk = 0; kk < 8; kk++) {
            float4 a0 = *(const float4*)&As[kk][ty * 8];
            float4 a1 = *(const float4*)&As[kk][ty * 8 + 4];
            float4 b0 = *(const float4*)&Bs[kk][tx * 8];
            float4 b1 = *(const float4*)&Bs[kk][tx * 8 + 4];
            float af[8] = {a0.x, a0.y, a0.z, a0.w, a1.x, a1.y, a1.z, a1.w};
            float bf[8] = {b0.x, b0.y, b0.z, b0.w, b1.x, b1.y, b1.z, b1.w};
            #pragma unroll
            for (int i = 0; i < 8; i++)
                #pragma unroll
                for (int j = 0; j < 8; j++)
                    acc[i][j] += af[i] * bf[j];
        }
        __syncthreads();
    }

    int row0 = blockIdx.y * 128 + ty * 8;
    int col0 = blockIdx.x * 128 + tx * 8;
    #pragma unroll
    for (int i = 0; i < 8; i++) {
        float* Crow = C + (size_t)(row0 + i) * Nn + col0;
        #pragma unroll
        for (int j = 0; j < 8; j++) {
            float v = acc[i][j];
            if (BIAS) v += bias[col0 + j];
            if (ACC)  v += Crow[j];
            Crow[j] = v;
        }
    }
}

// ---------------------------------------------------------------------------
// Temporal attention: one warp per (b, n, h). 32x32 scores over L, softmax, AV.
// q/k/v live in g_proj row offsets 0/128/256.
// ---------------------------------------------------------------------------
__global__ void __launch_bounds__(256) temporal_attn()
{
    __shared__ float4 Ks[8][32][4];
    __shared__ float4 Vs[8][32][4];

    int wid  = threadIdx.x >> 5;
    int lane = threadIdx.x & 31;
    int unit = blockIdx.x * 8 + wid;     // 0 .. B*N*H-1 = 31999
    int h  = unit & 7;
    int bn = unit >> 3;
    int n  = bn % N_;
    int b  = bn / N_;

    // lane == l (temporal position)
    size_t m = ((size_t)lane * B_ + b) * N_ + n;
    const float* row = g_proj + m * PROJW + h * DH_;

    float4 q[4];
    #pragma unroll
    for (int i = 0; i < 4; i++) q[i] = *(const float4*)(row + i * 4);
    #pragma unroll
    for (int i = 0; i < 4; i++) Ks[wid][lane][i] = *(const float4*)(row + 128 + i * 4);
    #pragma unroll
    for (int i = 0; i < 4; i++) Vs[wid][lane][i] = *(const float4*)(row + 256 + i * 4);
    __syncwarp();

    float s[32];
    #pragma unroll
    for (int mm = 0; mm < 32; mm++) {
        float a = 0.f;
        #pragma unroll
        for (int i = 0; i < 4; i++) {
            float4 kv = Ks[wid][mm][i];
            a += q[i].x * kv.x + q[i].y * kv.y + q[i].z * kv.z + q[i].w * kv.w;
        }
        s[mm] = a * 0.25f;   // 1/sqrt(16)
    }

    float mx = s[0];
    #pragma unroll
    for (int mm = 1; mm < 32; mm++) mx = fmaxf(mx, s[mm]);
    float sum = 0.f;
    #pragma unroll
    for (int mm = 0; mm < 32; mm++) { s[mm] = __expf(s[mm] - mx); sum += s[mm]; }
    float inv = 1.f / sum;

    float4 o[4];
    #pragma unroll
    for (int i = 0; i < 4; i++) o[i] = make_float4(0.f, 0.f, 0.f, 0.f);
    #pragma unroll
    for (int mm = 0; mm < 32; mm++) {
        float p = s[mm] * inv;
        #pragma unroll
        for (int i = 0; i < 4; i++) {
            float4 vv = Vs[wid][mm][i];
            o[i].x += p * vv.x; o[i].y += p * vv.y;
            o[i].z += p * vv.z; o[i].w += p * vv.w;
        }
    }

    float* orow = g_o + m * D_ + h * DH_;
    #pragma unroll
    for (int i = 0; i < 4; i++) *(float4*)(orow + i * 4) = o[i];
}

// ---------------------------------------------------------------------------
// Spatial attention: one thread per (token m, head h). 8 neighbors, softmax-8.
// sq/sk/sv at g_proj row offsets 384/512/640. Neighbor projections are the
// projections of the neighbor tokens (linearity of the projection).
// ---------------------------------------------------------------------------
__global__ void __launch_bounds__(256) spatial_attn(const int* __restrict__ route)
{
    int t = blockIdx.x * 256 + threadIdx.x;  // 0 .. M*H-1
    int h = t & 7;
    int m = t >> 3;
    int n = m % N_;
    size_t lbbase = (size_t)(m - n);         // (l*B + b) * N_

    const float* qrow = g_proj + (size_t)m * PROJW + 384 + h * DH_;
    float4 q[4];
    #pragma unroll
    for (int i = 0; i < 4; i++) q[i] = *(const float4*)(qrow + i * 4);

    int nb[8];
    float s[8];
    #pragma unroll
    for (int kk = 0; kk < 8; kk++) {
        nb[kk] = route[n * 8 + kk];
        const float* krow = g_proj + (lbbase + nb[kk]) * PROJW + 512 + h * DH_;
        float a = 0.f;
        #pragma unroll
        for (int i = 0; i < 4; i++) {
            float4 kv = *(const float4*)(krow + i * 4);
            a += q[i].x * kv.x + q[i].y * kv.y + q[i].z * kv.z + q[i].w * kv.w;
        }
        s[kk] = a * 0.25f;
    }

    float mx = s[0];
    #pragma unroll
    for (int kk = 1; kk < 8; kk++) mx = fmaxf(mx, s[kk]);
    float sum = 0.f;
    #pragma unroll
    for (int kk = 0; kk < 8; kk++) { s[kk] = __expf(s[kk] - mx); sum += s[kk]; }
    float inv = 1.f / sum;

    float4 o[4];
    #pragma unroll
    for (int i = 0; i < 4; i++) o[i] = make_float4(0.f, 0.f, 0.f, 0.f);
    #pragma unroll
    for (int kk = 0; kk < 8; kk++) {
        float p = s[kk] * inv;
        const float* vrow = g_proj + (lbbase + nb[kk]) * PROJW + 640 + h * DH_;
        #pragma unroll
        for (int i = 0; i < 4; i++) {
            float4 vv = *(const float4*)(vrow + i * 4);
            o[i].x += p * vv.x; o[i].y += p * vv.y;
            o[i].z += p * vv.z; o[i].w += p * vv.w;
        }
    }

    float* orow = g_so + (size_t)m * D_ + h * DH_;
    #pragma unroll
    for (int i = 0; i < 4; i++) *(float4*)(orow + i * 4) = o[i];
}

// ---------------------------------------------------------------------------
extern "C" void kernel_launch(void* const* d_in, const int* in_sizes, int n_in,
                              void* d_out, int out_size)
{
    const float* x       = (const float*)d_in[0];
    const int*   route   = (const int*)  d_in[1];
    const float* t_in_w  = (const float*)d_in[2];
    const float* t_in_b  = (const float*)d_in[3];
    const float* t_out_w = (const float*)d_in[4];
    const float* t_out_b = (const float*)d_in[5];
    const float* s_in_w  = (const float*)d_in[6];
    const float* s_in_b  = (const float*)d_in[7];
    const float* s_out_w = (const float*)d_in[8];
    const float* s_out_b = (const float*)d_in[9];
    float* out = (float*)d_out;

    float *gproj, *go, *gso, *gw, *gb, *gob;
    cudaGetSymbolAddress((void**)&gproj, g_proj);
    cudaGetSymbolAddress((void**)&go,    g_o);
    cudaGetSymbolAddress((void**)&gso,   g_so);
    cudaGetSymbolAddress((void**)&gw,    g_w);
    cudaGetSymbolAddress((void**)&gb,    g_b);
    cudaGetSymbolAddress((void**)&gob,   g_ob);

    // 1) pack weights
    prep_weights<<<388, 256>>>(t_in_w, t_in_b, s_in_w, s_in_b, t_out_b, s_out_b);

    // 2) fused projection: x(128000x128) @ Wt(128x768) + b -> g_proj
    sgemm_nt<false, true><<<dim3(6, M_ / 128), 256>>>(x, gw, gb, gproj, PROJW);

    // 3) temporal attention (warp per (b,n,h))
    temporal_attn<<<(B_ * N_ * H_) / 8, 256>>>();

    // 4) spatial attention (thread per (m,h))
    spatial_attn<<<(M_ * H_) / 256, 256>>>(route);

    // 5) out = o @ t_out_w^T + (t_out_b + s_out_b)
    sgemm_nt<false, true><<<dim3(1, M_ / 128), 256>>>(go, t_out_w, gob, out, D_);

    // 6) out += so @ s_out_w^T
    sgemm_nt<true, false><<<dim3(1, M_ / 128), 256>>>(gso, s_out_w, nullptr, out, D_);
}

// round 5
// speedup vs baseline: 1.6943x; 1.6943x over previous
#include <cuda_runtime.h>
#include <math.h>
#include <stdint.h>

// Problem constants
#define L_   32
#define B_   4
#define N_   1000
#define D_   128
#define K_   8
#define H_   8
#define DH_  16
#define M_   (L_ * B_ * N_)   // 128000 tokens
#define PROJW 768             // q|k|v|sq|sk|sv concatenated per token

// Scratch (device globals: allocation-free, graph-capturable)
__device__ float g_proj[(size_t)M_ * PROJW];  // ~393 MB
__device__ float g_att [(size_t)M_ * 256];    // [o | so] fused attn outputs
__device__ float g_w   [PROJW * D_];          // concat in-weights [768][128]
__device__ float g_wo  [D_ * 256];            // concat out-weights [128][256]
__device__ float g_b   [PROJW];               // concat in-biases
__device__ float g_ob  [D_];                  // t_out_b + s_out_b

// ---------------------------------------------------------------------------
// Pack weights/biases into contiguous buffers
// ---------------------------------------------------------------------------
__global__ void prep_weights(const float* __restrict__ t_in_w,
                             const float* __restrict__ t_in_b,
                             const float* __restrict__ s_in_w,
                             const float* __restrict__ s_in_b,
                             const float* __restrict__ t_out_w,
                             const float* __restrict__ t_out_b,
                             const float* __restrict__ s_out_w,
                             const float* __restrict__ s_out_b)
{
    int i = blockIdx.x * 256 + threadIdx.x;
    const int NW = 384 * 128;                 // 49152
    if (i < NW) {
        g_w[i] = t_in_w[i];
    } else if (i < 2 * NW) {
        g_w[i] = s_in_w[i - NW];
    } else if (i < 2 * NW + 128 * 256) {
        int j = i - 2 * NW;
        int n = j >> 8;
        int k = j & 255;
        g_wo[j] = (k < 128) ? t_out_w[n * 128 + k] : s_out_w[n * 128 + (k - 128)];
    } else {
        int j = i - (2 * NW + 128 * 256);
        if (j < 384)      g_b[j] = t_in_b[j];
        else if (j < 768) g_b[j] = s_in_b[j - 384];
        else if (j < 896) g_ob[j - 768] = t_out_b[j - 768] + s_out_b[j - 768];
    }
}

// ---------------------------------------------------------------------------
// TF32 tensor-core helpers
// ---------------------------------------------------------------------------
__device__ __forceinline__ uint32_t f2tf32(float f)
{
    uint32_t r;
    asm("cvt.rna.tf32.f32 %0, %1;" : "=r"(r) : "f"(f));
    return r;
}

__device__ __forceinline__ void mma_tf32(float* d, const uint32_t* a, const uint32_t* b)
{
    asm volatile(
        "mma.sync.aligned.m16n8k8.row.col.f32.tf32.tf32.f32 "
        "{%0,%1,%2,%3}, {%4,%5,%6,%7}, {%8,%9}, {%0,%1,%2,%3};"
        : "+f"(d[0]), "+f"(d[1]), "+f"(d[2]), "+f"(d[3])
        : "r"(a[0]), "r"(a[1]), "r"(a[2]), "r"(a[3]), "r"(b[0]), "r"(b[1]));
}

// ---------------------------------------------------------------------------
// TF32 GEMM (NT): C[m][n] = sum_k A[m][k] * Bw[n][k] + bias[n]
// A: M x KTOT row-major, Bw: Nn x KTOT row-major. 128x128 tile, 256 threads,
// 8 warps in 2x4 grid, warp tile 64(m) x 32(n). KTOT in {128, 256},
// processed in 128-wide chunks fully resident in smem.
// Smem stride 132 (== 4 mod 32) makes fragment LDS conflict-free.
// ---------------------------------------------------------------------------
#define GEMM_SMEM (2 * 128 * 132 * 4)

template<int KTOT>
__global__ void __launch_bounds__(256) tf32_gemm(const float* __restrict__ A,
                                                 const float* __restrict__ Bw,
                                                 const float* __restrict__ bias,
                                                 float* __restrict__ C,
                                                 int Nn)
{
    extern __shared__ uint32_t sm[];
    uint32_t* As = sm;               // [128][132]
    uint32_t* Bs = sm + 128 * 132;   // [128][132]

    const int tid   = threadIdx.x;
    const int warp  = tid >> 5;
    const int lane  = tid & 31;
    const int group = lane >> 2;     // 0..7
    const int tg    = lane & 3;      // 0..3
    const int wm    = (warp & 1) * 64;
    const int wn    = (warp >> 1) * 32;

    const int trow = tid >> 1;            // 0..127
    const int tcol = (tid & 1) * 64;      // 0 or 64

    const size_t arow0 = (size_t)blockIdx.y * 128;
    const size_t brow0 = (size_t)blockIdx.x * 128;

    float acc[4][4][4];
    #pragma unroll
    for (int mi = 0; mi < 4; mi++)
        #pragma unroll
        for (int ni = 0; ni < 4; ni++)
            #pragma unroll
            for (int r = 0; r < 4; r++) acc[mi][ni][r] = 0.f;

    #pragma unroll
    for (int kc = 0; kc < KTOT; kc += 128) {
        if (kc) __syncthreads();

        // Load 128x128 chunks of A and Bw, convert to tf32, store to smem
        const float* Ag = A  + (arow0 + trow) * KTOT + kc + tcol;
        const float* Bg = Bw + (brow0 + trow) * KTOT + kc + tcol;
        uint32_t* Asp = As + trow * 132 + tcol;
        uint32_t* Bsp = Bs + trow * 132 + tcol;
        #pragma unroll
        for (int i = 0; i < 16; i++) {
            float4 a = *(const float4*)(Ag + i * 4);
            float4 b = *(const float4*)(Bg + i * 4);
            uint4 ua = make_uint4(f2tf32(a.x), f2tf32(a.y), f2tf32(a.z), f2tf32(a.w));
            uint4 ub = make_uint4(f2tf32(b.x), f2tf32(b.y), f2tf32(b.z), f2tf32(b.w));
            *(uint4*)(Asp + i * 4) = ua;
            *(uint4*)(Bsp + i * 4) = ub;
        }
        __syncthreads();

        #pragma unroll
        for (int k0 = 0; k0 < 128; k0 += 8) {
            uint32_t af[4][4];
            uint32_t bf[4][2];
            #pragma unroll
            for (int mi = 0; mi < 4; mi++) {
                const uint32_t* p = As + (wm + mi * 16 + group) * 132 + k0 + tg;
                af[mi][0] = p[0];
                af[mi][1] = p[8 * 132];
                af[mi][2] = p[4];
                af[mi][3] = p[8 * 132 + 4];
            }
            #pragma unroll
            for (int ni = 0; ni < 4; ni++) {
                const uint32_t* p = Bs + (wn + ni * 8 + group) * 132 + k0 + tg;
                bf[ni][0] = p[0];
                bf[ni][1] = p[4];
            }
            #pragma unroll
            for (int mi = 0; mi < 4; mi++)
                #pragma unroll
                for (int ni = 0; ni < 4; ni++)
                    mma_tf32(acc[mi][ni], af[mi], bf[ni]);
        }
    }

    // Epilogue: bias + store (float2 per fragment row-pair)
    const int row0 = (int)arow0 + wm + group;
    const int col0 = (int)brow0 + wn + tg * 2;
    #pragma unroll
    for (int ni = 0; ni < 4; ni++) {
        int c = col0 + ni * 8;
        float b0 = bias[c], b1 = bias[c + 1];
        #pragma unroll
        for (int mi = 0; mi < 4; mi++) {
            int r = row0 + mi * 16;
            float2 v0 = make_float2(acc[mi][ni][0] + b0, acc[mi][ni][1] + b1);
            float2 v1 = make_float2(acc[mi][ni][2] + b0, acc[mi][ni][3] + b1);
            *(float2*)&C[(size_t)r * Nn + c]       = v0;
            *(float2*)&C[(size_t)(r + 8) * Nn + c] = v1;
        }
    }
}

// ---------------------------------------------------------------------------
// Temporal attention: one warp per (b, n, h). 32x32 scores over L, softmax, AV.
// q/k/v live in g_proj row offsets 0/128/256. Output -> g_att cols [0,128).
// ---------------------------------------------------------------------------
__global__ void __launch_bounds__(256) temporal_attn()
{
    __shared__ float4 Ks[8][32][4];
    __shared__ float4 Vs[8][32][4];

    int wid  = threadIdx.x >> 5;
    int lane = threadIdx.x & 31;
    int unit = blockIdx.x * 8 + wid;     // 0 .. B*N*H-1
    int h  = unit & 7;
    int bn = unit >> 3;
    int n  = bn % N_;
    int b  = bn / N_;

    // lane == l (temporal position)
    size_t m = ((size_t)lane * B_ + b) * N_ + n;
    const float* row = g_proj + m * PROJW + h * DH_;

    float4 q[4];
    #pragma unroll
    for (int i = 0; i < 4; i++) q[i] = *(const float4*)(row + i * 4);
    #pragma unroll
    for (int i = 0; i < 4; i++) Ks[wid][lane][i] = *(const float4*)(row + 128 + i * 4);
    #pragma unroll
    for (int i = 0; i < 4; i++) Vs[wid][lane][i] = *(const float4*)(row + 256 + i * 4);
    __syncwarp();

    float s[32];
    #pragma unroll
    for (int mm = 0; mm < 32; mm++) {
        float a = 0.f;
        #pragma unroll
        for (int i = 0; i < 4; i++) {
            float4 kv = Ks[wid][mm][i];
            a += q[i].x * kv.x + q[i].y * kv.y + q[i].z * kv.z + q[i].w * kv.w;
        }
        s[mm] = a * 0.25f;   // 1/sqrt(16)
    }

    float mx = s[0];
    #pragma unroll
    for (int mm = 1; mm < 32; mm++) mx = fmaxf(mx, s[mm]);
    float sum = 0.f;
    #pragma unroll
    for (int mm = 0; mm < 32; mm++) { s[mm] = __expf(s[mm] - mx); sum += s[mm]; }
    float inv = 1.f / sum;

    float4 o[4];
    #pragma unroll
    for (int i = 0; i < 4; i++) o[i] = make_float4(0.f, 0.f, 0.f, 0.f);
    #pragma unroll
    for (int mm = 0; mm < 32; mm++) {
        float p = s[mm] * inv;
        #pragma unroll
        for (int i = 0; i < 4; i++) {
            float4 vv = Vs[wid][mm][i];
            o[i].x += p * vv.x; o[i].y += p * vv.y;
            o[i].z += p * vv.z; o[i].w += p * vv.w;
        }
    }

    float* orow = g_att + m * 256 + h * DH_;
    #pragma unroll
    for (int i = 0; i < 4; i++) *(float4*)(orow + i * 4) = o[i];
}

// ---------------------------------------------------------------------------
// Spatial attention: one thread per (token m, head h). 8 neighbors, softmax-8.
// sq/sk/sv at g_proj row offsets 384/512/640. Output -> g_att cols [128,256).
// ---------------------------------------------------------------------------
__global__ void __launch_bounds__(256) spatial_attn(const int* __restrict__ route)
{
    int t = blockIdx.x * 256 + threadIdx.x;  // 0 .. M*H-1
    int h = t & 7;
    int m = t >> 3;
    int n = m % N_;
    size_t lbbase = (size_t)(m - n);         // (l*B + b) * N_

    const float* qrow = g_proj + (size_t)m * PROJW + 384 + h * DH_;
    float4 q[4];
    #pragma unroll
    for (int i = 0; i < 4; i++) q[i] = *(const float4*)(qrow + i * 4);

    int nb[8];
    float s[8];
    #pragma unroll
    for (int kk = 0; kk < 8; kk++) {
        nb[kk] = route[n * 8 + kk];
        const float* krow = g_proj + (lbbase + nb[kk]) * PROJW + 512 + h * DH_;
        float a = 0.f;
        #pragma unroll
        for (int i = 0; i < 4; i++) {
            float4 kv = *(const float4*)(krow + i * 4);
            a += q[i].x * kv.x + q[i].y * kv.y + q[i].z * kv.z + q[i].w * kv.w;
        }
        s[kk] = a * 0.25f;
    }

    float mx = s[0];
    #pragma unroll
    for (int kk = 1; kk < 8; kk++) mx = fmaxf(mx, s[kk]);
    float sum = 0.f;
    #pragma unroll
    for (int kk = 0; kk < 8; kk++) { s[kk] = __expf(s[kk] - mx); sum += s[kk]; }
    float inv = 1.f / sum;

    float4 o[4];
    #pragma unroll
    for (int i = 0; i < 4; i++) o[i] = make_float4(0.f, 0.f, 0.f, 0.f);
    #pragma unroll
    for (int kk = 0; kk < 8; kk++) {
        float p = s[kk] * inv;
        const float* vrow = g_proj + (lbbase + nb[kk]) * PROJW + 640 + h * DH_;
        #pragma unroll
        for (int i = 0; i < 4; i++) {
            float4 vv = *(const float4*)(vrow + i * 4);
            o[i].x += p * vv.x; o[i].y += p * vv.y;
            o[i].z += p * vv.z; o[i].w += p * vv.w;
        }
    }

    float* orow = g_att + (size_t)m * 256 + 128 + h * DH_;
    #pragma unroll
    for (int i = 0; i < 4; i++) *(float4*)(orow + i * 4) = o[i];
}

// ---------------------------------------------------------------------------
extern "C" void kernel_launch(void* const* d_in, const int* in_sizes, int n_in,
                              void* d_out, int out_size)
{
    const float* x       = (const float*)d_in[0];
    const int*   route   = (const int*)  d_in[1];
    const float* t_in_w  = (const float*)d_in[2];
    const float* t_in_b  = (const float*)d_in[3];
    const float* t_out_w = (const float*)d_in[4];
    const float* t_out_b = (const float*)d_in[5];
    const float* s_in_w  = (const float*)d_in[6];
    const float* s_in_b  = (const float*)d_in[7];
    const float* s_out_w = (const float*)d_in[8];
    const float* s_out_b = (const float*)d_in[9];
    float* out = (float*)d_out;

    float *gproj, *gatt, *gw, *gwo, *gb, *gob;
    cudaGetSymbolAddress((void**)&gproj, g_proj);
    cudaGetSymbolAddress((void**)&gatt,  g_att);
    cudaGetSymbolAddress((void**)&gw,    g_w);
    cudaGetSymbolAddress((void**)&gwo,   g_wo);
    cudaGetSymbolAddress((void**)&gb,    g_b);
    cudaGetSymbolAddress((void**)&gob,   g_ob);

    cudaFuncSetAttribute(tf32_gemm<128>, cudaFuncAttributeMaxDynamicSharedMemorySize, GEMM_SMEM);
    cudaFuncSetAttribute(tf32_gemm<256>, cudaFuncAttributeMaxDynamicSharedMemorySize, GEMM_SMEM);

    // 1) pack weights: 2*49152 + 32768 + 896 = 131968 items
    prep_weights<<<516, 256>>>(t_in_w, t_in_b, s_in_w, s_in_b,
                               t_out_w, t_out_b, s_out_w, s_out_b);

    // 2) fused projection: x(128000x128) @ g_w^T(128x768) + g_b -> g_proj
    tf32_gemm<128><<<dim3(6, M_ / 128), 256, GEMM_SMEM>>>(x, gw, gb, gproj, PROJW);

    // 3) temporal attention (warp per (b,n,h)) -> g_att[:, 0:128]
    temporal_attn<<<(B_ * N_ * H_) / 8, 256>>>();

    // 4) spatial attention (thread per (m,h)) -> g_att[:, 128:256]
    spatial_attn<<<(M_ * H_) / 256, 256>>>(route);

    // 5) out = g_att(128000x256) @ g_wo^T(256x128) + (t_out_b + s_out_b)
    tf32_gemm<256><<<dim3(1, M_ / 128), 256, GEMM_SMEM>>>(gatt, gwo, gob, out, D_);
}

// round 8
// speedup vs baseline: 2.0329x; 1.1999x over previous
#include <cuda_runtime.h>
#include <math.h>
#include <stdint.h>

// Problem constants
#define L_   32
#define B_   4
#define N_   1000
#define D_   128
#define K_   8
#define H_   8
#define DH_  16
#define M_   (L_ * B_ * N_)   // 128000 tokens
#define PROJW 768             // q|k|v|sq|sk|sv concatenated per token

// Scratch (device globals: allocation-free, graph-capturable)
__device__ float g_proj[(size_t)M_ * PROJW];  // ~393 MB
__device__ float g_att [(size_t)M_ * 256];    // [o | so] fused attn outputs
__device__ float g_w   [PROJW * D_];          // concat in-weights [768][128]
__device__ float g_wo  [D_ * 256];            // concat out-weights [128][256]
__device__ float g_b   [PROJW];               // concat in-biases
__device__ float g_ob  [D_];                  // t_out_b + s_out_b

// ---------------------------------------------------------------------------
// Pack weights/biases into contiguous buffers
// ---------------------------------------------------------------------------
__global__ void prep_weights(const float* __restrict__ t_in_w,
                             const float* __restrict__ t_in_b,
                             const float* __restrict__ s_in_w,
                             const float* __restrict__ s_in_b,
                             const float* __restrict__ t_out_w,
                             const float* __restrict__ t_out_b,
                             const float* __restrict__ s_out_w,
                             const float* __restrict__ s_out_b)
{
    int i = blockIdx.x * 256 + threadIdx.x;
    const int NW = 384 * 128;                 // 49152
    if (i < NW) {
        g_w[i] = t_in_w[i];
    } else if (i < 2 * NW) {
        g_w[i] = s_in_w[i - NW];
    } else if (i < 2 * NW + 128 * 256) {
        int j = i - 2 * NW;
        int n = j >> 8;
        int k = j & 255;
        g_wo[j] = (k < 128) ? t_out_w[n * 128 + k] : s_out_w[n * 128 + (k - 128)];
    } else {
        int j = i - (2 * NW + 128 * 256);
        if (j < 384)      g_b[j] = t_in_b[j];
        else if (j < 768) g_b[j] = s_in_b[j - 384];
        else if (j < 896) g_ob[j - 768] = t_out_b[j - 768] + s_out_b[j - 768];
    }
}

// ---------------------------------------------------------------------------
// TF32 tensor-core helpers
// ---------------------------------------------------------------------------
__device__ __forceinline__ uint32_t f2tf32(float f)
{
    uint32_t r;
    asm("cvt.rna.tf32.f32 %0, %1;" : "=r"(r) : "f"(f));
    return r;
}

__device__ __forceinline__ void mma_tf32(float* d, const uint32_t* a, const uint32_t* b)
{
    asm volatile(
        "mma.sync.aligned.m16n8k8.row.col.f32.tf32.tf32.f32 "
        "{%0,%1,%2,%3}, {%4,%5,%6,%7}, {%8,%9}, {%0,%1,%2,%3};"
        : "+f"(d[0]), "+f"(d[1]), "+f"(d[2]), "+f"(d[3])
        : "r"(a[0]), "r"(a[1]), "r"(a[2]), "r"(a[3]), "r"(b[0]), "r"(b[1]));
}

#define GEMM_SMEM (2 * 128 * 132 * 4)

// ---------------------------------------------------------------------------
// Projection GEMM, A-resident: one block per 128-row tile of x (grid 1000).
// A tile loaded ONCE to smem; loop over all 6 weight N-tiles (L2-hot).
// g_proj[m][c] = sum_k x[m][k] * g_w[c][k] + g_b[c]
// ---------------------------------------------------------------------------
__global__ void __launch_bounds__(256) tf32_gemm_proj(const float* __restrict__ A)
{
    extern __shared__ uint32_t sm[];
    uint32_t* As = sm;               // [128][132]
    uint32_t* Bs = sm + 128 * 132;   // [128][132]

    const int tid   = threadIdx.x;
    const int warp  = tid >> 5;
    const int lane  = tid & 31;
    const int group = lane >> 2;
    const int tg    = lane & 3;
    const int wm    = (warp & 1) * 64;
    const int wn    = (warp >> 1) * 32;

    const int trow = tid >> 1;
    const int tcol = (tid & 1) * 64;

    const size_t arow0 = (size_t)blockIdx.x * 128;

    // Load A tile once
    {
        const float* Ag = A + (arow0 + trow) * 128 + tcol;
        uint32_t* Asp = As + trow * 132 + tcol;
        #pragma unroll
        for (int i = 0; i < 16; i++) {
            float4 a = *(const float4*)(Ag + i * 4);
            *(uint4*)(Asp + i * 4) =
                make_uint4(f2tf32(a.x), f2tf32(a.y), f2tf32(a.z), f2tf32(a.w));
        }
    }

    for (int nt = 0; nt < 6; nt++) {
        if (nt) __syncthreads();   // previous compute done before Bs overwrite
        {
            const float* Bg = g_w + (nt * 128 + trow) * 128 + tcol;
            uint32_t* Bsp = Bs + trow * 132 + tcol;
            #pragma unroll
            for (int i = 0; i < 16; i++) {
                float4 b = *(const float4*)(Bg + i * 4);
                *(uint4*)(Bsp + i * 4) =
                    make_uint4(f2tf32(b.x), f2tf32(b.y), f2tf32(b.z), f2tf32(b.w));
            }
        }
        __syncthreads();

        float acc[4][4][4];
        #pragma unroll
        for (int mi = 0; mi < 4; mi++)
            #pragma unroll
            for (int ni = 0; ni < 4; ni++)
                #pragma unroll
                for (int r = 0; r < 4; r++) acc[mi][ni][r] = 0.f;

        #pragma unroll
        for (int k0 = 0; k0 < 128; k0 += 8) {
            uint32_t af[4][4];
            uint32_t bf[4][2];
            #pragma unroll
            for (int mi = 0; mi < 4; mi++) {
                const uint32_t* p = As + (wm + mi * 16 + group) * 132 + k0 + tg;
                af[mi][0] = p[0];
                af[mi][1] = p[8 * 132];
                af[mi][2] = p[4];
                af[mi][3] = p[8 * 132 + 4];
            }
            #pragma unroll
            for (int ni = 0; ni < 4; ni++) {
                const uint32_t* p = Bs + (wn + ni * 8 + group) * 132 + k0 + tg;
                bf[ni][0] = p[0];
                bf[ni][1] = p[4];
            }
            #pragma unroll
            for (int mi = 0; mi < 4; mi++)
                #pragma unroll
                for (int ni = 0; ni < 4; ni++)
                    mma_tf32(acc[mi][ni], af[mi], bf[ni]);
        }

        // Epilogue
        const int row0 = (int)arow0 + wm + group;
        const int col0 = nt * 128 + wn + tg * 2;
        #pragma unroll
        for (int ni = 0; ni < 4; ni++) {
            int c = col0 + ni * 8;
            float b0 = g_b[c], b1 = g_b[c + 1];
            #pragma unroll
            for (int mi = 0; mi < 4; mi++) {
                int r = row0 + mi * 16;
                *(float2*)&g_proj[(size_t)r * PROJW + c] =
                    make_float2(acc[mi][ni][0] + b0, acc[mi][ni][1] + b1);
                *(float2*)&g_proj[(size_t)(r + 8) * PROJW + c] =
                    make_float2(acc[mi][ni][2] + b0, acc[mi][ni][3] + b1);
            }
        }
    }
}

// ---------------------------------------------------------------------------
// Generic TF32 GEMM (NT) for the fused output projection (KTOT=256).
// ---------------------------------------------------------------------------
template<int KTOT>
__global__ void __launch_bounds__(256) tf32_gemm(const float* __restrict__ A,
                                                 const float* __restrict__ Bw,
                                                 const float* __restrict__ bias,
                                                 float* __restrict__ C,
                                                 int Nn)
{
    extern __shared__ uint32_t sm[];
    uint32_t* As = sm;
    uint32_t* Bs = sm + 128 * 132;

    const int tid   = threadIdx.x;
    const int warp  = tid >> 5;
    const int lane  = tid & 31;
    const int group = lane >> 2;
    const int tg    = lane & 3;
    const int wm    = (warp & 1) * 64;
    const int wn    = (warp >> 1) * 32;

    const int trow = tid >> 1;
    const int tcol = (tid & 1) * 64;

    const size_t arow0 = (size_t)blockIdx.y * 128;
    const size_t brow0 = (size_t)blockIdx.x * 128;

    float acc[4][4][4];
    #pragma unroll
    for (int mi = 0; mi < 4; mi++)
        #pragma unroll
        for (int ni = 0; ni < 4; ni++)
            #pragma unroll
            for (int r = 0; r < 4; r++) acc[mi][ni][r] = 0.f;

    #pragma unroll
    for (int kc = 0; kc < KTOT; kc += 128) {
        if (kc) __syncthreads();

        const float* Ag = A  + (arow0 + trow) * KTOT + kc + tcol;
        const float* Bg = Bw + (brow0 + trow) * KTOT + kc + tcol;
        uint32_t* Asp = As + trow * 132 + tcol;
        uint32_t* Bsp = Bs + trow * 132 + tcol;
        #pragma unroll
        for (int i = 0; i < 16; i++) {
            float4 a = *(const float4*)(Ag + i * 4);
            float4 b = *(const float4*)(Bg + i * 4);
            *(uint4*)(Asp + i * 4) = make_uint4(f2tf32(a.x), f2tf32(a.y), f2tf32(a.z), f2tf32(a.w));
            *(uint4*)(Bsp + i * 4) = make_uint4(f2tf32(b.x), f2tf32(b.y), f2tf32(b.z), f2tf32(b.w));
        }
        __syncthreads();

        #pragma unroll
        for (int k0 = 0; k0 < 128; k0 += 8) {
            uint32_t af[4][4];
            uint32_t bf[4][2];
            #pragma unroll
            for (int mi = 0; mi < 4; mi++) {
                const uint32_t* p = As + (wm + mi * 16 + group) * 132 + k0 + tg;
                af[mi][0] = p[0];
                af[mi][1] = p[8 * 132];
                af[mi][2] = p[4];
                af[mi][3] = p[8 * 132 + 4];
            }
            #pragma unroll
            for (int ni = 0; ni < 4; ni++) {
                const uint32_t* p = Bs + (wn + ni * 8 + group) * 132 + k0 + tg;
                bf[ni][0] = p[0];
                bf[ni][1] = p[4];
            }
            #pragma unroll
            for (int mi = 0; mi < 4; mi++)
                #pragma unroll
                for (int ni = 0; ni < 4; ni++)
                    mma_tf32(acc[mi][ni], af[mi], bf[ni]);
        }
    }

    const int row0 = (int)arow0 + wm + group;
    const int col0 = (int)brow0 + wn + tg * 2;
    #pragma unroll
    for (int ni = 0; ni < 4; ni++) {
        int c = col0 + ni * 8;
        float b0 = bias[c], b1 = bias[c + 1];
        #pragma unroll
        for (int mi = 0; mi < 4; mi++) {
            int r = row0 + mi * 16;
            *(float2*)&C[(size_t)r * Nn + c] =
                make_float2(acc[mi][ni][0] + b0, acc[mi][ni][1] + b1);
            *(float2*)&C[(size_t)(r + 8) * Nn + c] =
                make_float2(acc[mi][ni][2] + b0, acc[mi][ni][3] + b1);
        }
    }
}

// ---------------------------------------------------------------------------
// Temporal attention: one block per (b, n). Cooperative coalesced load of all
// 32 rows x (q|k|v) into smem, then warp h computes head h (smem reads are
// all-lane broadcasts -> conflict-free). Output -> g_att cols [0,128).
// ---------------------------------------------------------------------------
#define TEMP_STRIDE 388   // 384 + 4 pad (floats)
#define TEMP_SMEM   (32 * TEMP_STRIDE * 4)

__global__ void __launch_bounds__(256) temporal_attn()
{
    extern __shared__ float S[];   // [32][TEMP_STRIDE]

    const int tid  = threadIdx.x;
    const int wid  = tid >> 5;     // head
    const int lane = tid & 31;     // l (temporal position)
    const int n = blockIdx.x % N_;
    const int b = blockIdx.x / N_;

    // Coalesced load: 32 rows x 384 floats (96 float4 per row)
    #pragma unroll
    for (int i = 0; i < 12; i++) {
        int fid = i * 256 + tid;        // 0..3071
        int r   = fid / 96;
        int c4  = fid % 96;
        size_t m = ((size_t)r * B_ + b) * N_ + n;
        float4 v = *(const float4*)(g_proj + m * PROJW + c4 * 4);
        *(float4*)(S + r * TEMP_STRIDE + c4 * 4) = v;
    }
    __syncthreads();

    const int hoff = wid * DH_;
    float4 q[4];
    #pragma unroll
    for (int i = 0; i < 4; i++)
        q[i] = *(const float4*)(S + lane * TEMP_STRIDE + hoff + i * 4);

    float s[32];
    #pragma unroll
    for (int mm = 0; mm < 32; mm++) {
        const float* kr = S + mm * TEMP_STRIDE + 128 + hoff;
        float a = 0.f;
        #pragma unroll
        for (int i = 0; i < 4; i++) {
            float4 kv = *(const float4*)(kr + i * 4);   // broadcast
            a += q[i].x * kv.x + q[i].y * kv.y + q[i].z * kv.z + q[i].w * kv.w;
        }
        s[mm] = a * 0.25f;
    }

    float mx = s[0];
    #pragma unroll
    for (int mm = 1; mm < 32; mm++) mx = fmaxf(mx, s[mm]);
    float sum = 0.f;
    #pragma unroll
    for (int mm = 0; mm < 32; mm++) { s[mm] = __expf(s[mm] - mx); sum += s[mm]; }
    float inv = 1.f / sum;

    float4 o[4];
    #pragma unroll
    for (int i = 0; i < 4; i++) o[i] = make_float4(0.f, 0.f, 0.f, 0.f);
    #pragma unroll
    for (int mm = 0; mm < 32; mm++) {
        float p = s[mm] * inv;
        const float* vr = S + mm * TEMP_STRIDE + 256 + hoff;
        #pragma unroll
        for (int i = 0; i < 4; i++) {
            float4 vv = *(const float4*)(vr + i * 4);   // broadcast
            o[i].x += p * vv.x; o[i].y += p * vv.y;
            o[i].z += p * vv.z; o[i].w += p * vv.w;
        }
    }

    size_t m = ((size_t)lane * B_ + b) * N_ + n;
    float* orow = g_att + m * 256 + hoff;
    #pragma unroll
    for (int i = 0; i < 4; i++) *(float4*)(orow + i * 4) = o[i];
}

// ---------------------------------------------------------------------------
// Spatial attention: one warp per token m (all 8 heads). Neighbor sk/sv rows
// staged to smem with fully-coalesced 512B warp loads. Lanes compute the 64
// (h,kk) scores (2 each), butterfly softmax in 8-lane groups, then each lane
// produces 4 output columns. Output -> g_att cols [128,256).
// ---------------------------------------------------------------------------
#define SKV_STRIDE 132
#define SP_SK(w)  (Ssp + (w) * (8 * SKV_STRIDE))
#define SP_SV(w)  (Ssp + 8 * (8 * SKV_STRIDE) + (w) * (8 * SKV_STRIDE))
#define SP_SQ(w)  (Ssp + 16 * (8 * SKV_STRIDE) + (w) * 128)
#define SP_P(w)   (Ssp + 16 * (8 * SKV_STRIDE) + 8 * 128 + (w) * 72)
#define SPAT_SMEM ((16 * (8 * SKV_STRIDE) + 8 * 128 + 8 * 72) * 4)

__global__ void __launch_bounds__(256) spatial_attn(const int* __restrict__ route)
{
    extern __shared__ float Ssp[];

    const int tid  = threadIdx.x;
    const int w    = tid >> 5;
    const int lane = tid & 31;
    const size_t m = (size_t)blockIdx.x * 8 + w;
    const int n = (int)(m % N_);
    const size_t lbbase = m - n;

    float* sk = SP_SK(w);
    float* sv = SP_SV(w);
    float* sq = SP_SQ(w);
    float* sp = SP_P(w);

    // Stage sq (coalesced 512B)
    *(float4*)(sq + lane * 4) =
        *(const float4*)(g_proj + m * PROJW + 384 + lane * 4);

    // Stage 8 neighbor sk/sv rows (each a coalesced 512B warp load)
    int nbv = (lane < 8) ? route[n * 8 + lane] : 0;
    #pragma unroll
    for (int kk = 0; kk < 8; kk++) {
        int nb = __shfl_sync(0xffffffffu, nbv, kk);
        const float* r = g_proj + (lbbase + nb) * PROJW;
        float4 k4 = *(const float4*)(r + 512 + lane * 4);
        float4 v4 = *(const float4*)(r + 640 + lane * 4);
        *(float4*)(sk + kk * SKV_STRIDE + lane * 4) = k4;
        *(float4*)(sv + kk * SKV_STRIDE + lane * 4) = v4;
    }
    __syncwarp();

    // Scores: lane handles (h0, kk) and (h0+4, kk)
    const int h0 = lane >> 3;
    const int kk = lane & 7;
    float s0 = 0.f, s1 = 0.f;
    #pragma unroll
    for (int i = 0; i < 4; i++) {
        float4 qa = *(const float4*)(sq + h0 * 16 + i * 4);
        float4 ka = *(const float4*)(sk + kk * SKV_STRIDE + h0 * 16 + i * 4);
        s0 += qa.x * ka.x + qa.y * ka.y + qa.z * ka.z + qa.w * ka.w;
        float4 qb = *(const float4*)(sq + (h0 + 4) * 16 + i * 4);
        float4 kb = *(const float4*)(sk + kk * SKV_STRIDE + (h0 + 4) * 16 + i * 4);
        s1 += qb.x * kb.x + qb.y * kb.y + qb.z * kb.z + qb.w * kb.w;
    }
    s0 *= 0.25f; s1 *= 0.25f;

    // Softmax over kk within 8-lane groups
    float m0 = s0, m1 = s1;
    #pragma unroll
    for (int d = 1; d < 8; d <<= 1) {
        m0 = fmaxf(m0, __shfl_xor_sync(0xffffffffu, m0, d));
        m1 = fmaxf(m1, __shfl_xor_sync(0xffffffffu, m1, d));
    }
    float e0 = __expf(s0 - m0), e1 = __expf(s1 - m1);
    float t0 = e0, t1 = e1;
    #pragma unroll
    for (int d = 1; d < 8; d <<= 1) {
        t0 += __shfl_xor_sync(0xffffffffu, t0, d);
        t1 += __shfl_xor_sync(0xffffffffu, t1, d);
    }
    sp[h0 * 9 + kk]       = e0 / t0;
    sp[(h0 + 4) * 9 + kk] = e1 / t1;
    __syncwarp();

    // Output: lane produces columns 4*lane .. 4*lane+3 (head = lane>>2)
    const int hc = lane >> 2;
    float4 o = make_float4(0.f, 0.f, 0.f, 0.f);
    #pragma unroll
    for (int k2 = 0; k2 < 8; k2++) {
        float p = sp[hc * 9 + k2];
        float4 v = *(const float4*)(sv + k2 * SKV_STRIDE + lane * 4);
        o.x += p * v.x; o.y += p * v.y; o.z += p * v.z; o.w += p * v.w;
    }
    *(float4*)(g_att + m * 256 + 128 + lane * 4) = o;
}

// ---------------------------------------------------------------------------
extern "C" void kernel_launch(void* const* d_in, const int* in_sizes, int n_in,
                              void* d_out, int out_size)
{
    const float* x       = (const float*)d_in[0];
    const int*   route   = (const int*)  d_in[1];
    const float* t_in_w  = (const float*)d_in[2];
    const float* t_in_b  = (const float*)d_in[3];
    const float* t_out_w = (const float*)d_in[4];
    const float* t_out_b = (const float*)d_in[5];
    const float* s_in_w  = (const float*)d_in[6];
    const float* s_in_b  = (const float*)d_in[7];
    const float* s_out_w = (const float*)d_in[8];
    const float* s_out_b = (const float*)d_in[9];
    float* out = (float*)d_out;

    float *gatt, *gwo, *gob;
    cudaGetSymbolAddress((void**)&gatt, g_att);
    cudaGetSymbolAddress((void**)&gwo,  g_wo);
    cudaGetSymbolAddress((void**)&gob,  g_ob);

    cudaFuncSetAttribute(tf32_gemm_proj, cudaFuncAttributeMaxDynamicSharedMemorySize, GEMM_SMEM);
    cudaFuncSetAttribute(tf32_gemm<256>, cudaFuncAttributeMaxDynamicSharedMemorySize, GEMM_SMEM);
    cudaFuncSetAttribute(temporal_attn,  cudaFuncAttributeMaxDynamicSharedMemorySize, TEMP_SMEM);
    cudaFuncSetAttribute(spatial_attn,   cudaFuncAttributeMaxDynamicSharedMemorySize, SPAT_SMEM);

    // 1) pack weights
    prep_weights<<<516, 256>>>(t_in_w, t_in_b, s_in_w, s_in_b,
                               t_out_w, t_out_b, s_out_w, s_out_b);

    // 2) fused projection (A-resident): x(128000x128) @ g_w^T + g_b -> g_proj
    tf32_gemm_proj<<<M_ / 128, 256, GEMM_SMEM>>>(x);

    // 3) temporal attention (block per (b,n)) -> g_att[:, 0:128]
    temporal_attn<<<B_ * N_, 256, TEMP_SMEM>>>();

    // 4) spatial attention (warp per token) -> g_att[:, 128:256]
    spatial_attn<<<M_ / 8, 256, SPAT_SMEM>>>(route);

    // 5) out = g_att(128000x256) @ g_wo^T(256x128) + (t_out_b + s_out_b)
    tf32_gemm<256><<<dim3(1, M_ / 128), 256, GEMM_SMEM>>>(gatt, gwo, gob, out, D_);
}